// round 3
// baseline (speedup 1.0000x reference)
#include <cuda_runtime.h>
#include <math.h>
#include <math_constants.h>

#define B_   2
#define T_   2048
#define DIM  2048
#define NH   16
#define NKV  4
#define HD   128
#define KD   512           // NKV*HD
#define EPSF 1.1920928955078125e-07f

// ---------------- scratch (static device memory; no allocation) ----------------
__device__ float g_q [B_*T_*DIM];        // q after proj / norm / rope (natural)
__device__ float g_k [B_*T_*KD];         // k after proj (natural)
__device__ float g_kT[B_*NKV*HD*T_];     // k after norm/rope, transposed [b][kv][d][t]
__device__ float g_v [B_*T_*KD];         // v (natural)
__device__ float g_y [B_*T_*DIM];        // attention output (natural)
__device__ float g_cos[T_*(HD/2)];
__device__ float g_sin[T_*(HD/2)];

// ---------------- RoPE tables (double, matching numpy f64 path) ----------------
__global__ void rope_table_kernel() {
    int idx = blockIdx.x * blockDim.x + threadIdx.x;
    if (idx >= T_ * (HD/2)) return;
    int t = idx / (HD/2), j = idx % (HD/2);
    // T=2048 > 1024  =>  base = 10000 * 2^(hd/(hd-2))
    double base = 10000.0 * exp2((double)HD / (double)(HD - 2));
    double e    = (double)(2 * j) / (double)HD;
    double invf = 1.0 / pow(base, e);
    double fr   = (double)t * invf;
    g_cos[idx] = (float)cos(fr);
    g_sin[idx] = (float)sin(fr);
}

// ---------------- RMSNorm + RoPE (+gain) for Q : one warp per (b,t,h) row ----------------
__global__ void rmsnorm_rope_q_kernel(float* __restrict__ q, const float* __restrict__ gain) {
    int w = threadIdx.x >> 5, l = threadIdx.x & 31;
    int row = blockIdx.x * 8 + w;           // (b*T + t)*NH + h
    int h = row % NH;
    int t = (row / NH) % T_;
    float* p = q + (size_t)row * HD;
    float x1a = p[l], x1b = p[l+32], x2a = p[l+64], x2b = p[l+96];
    float ss = x1a*x1a + x1b*x1b + x2a*x2a + x2b*x2b;
    #pragma unroll
    for (int o = 16; o; o >>= 1) ss += __shfl_xor_sync(0xffffffffu, ss, o);
    float r = rsqrtf(ss * (1.0f/HD) + EPSF);
    x1a *= r; x1b *= r; x2a *= r; x2b *= r;
    float c1 = g_cos[t*(HD/2)+l],    s1 = g_sin[t*(HD/2)+l];
    float c2 = g_cos[t*(HD/2)+l+32], s2 = g_sin[t*(HD/2)+l+32];
    float gn = gain[h];
    p[l]    = ( x1a*c1 + x2a*s1) * gn;
    p[l+32] = ( x1b*c2 + x2b*s2) * gn;
    p[l+64] = (-x1a*s1 + x2a*c1) * gn;
    p[l+96] = (-x1b*s2 + x2b*c2) * gn;
}

// ---------------- RMSNorm + RoPE for K, writes transposed layout ----------------
__global__ void rmsnorm_rope_k_kernel(const float* __restrict__ k) {
    int w = threadIdx.x >> 5, l = threadIdx.x & 31;
    int row = blockIdx.x * 8 + w;           // (b*T + t)*NKV + kv
    int kv = row % NKV;
    int bt = row / NKV;
    int t = bt % T_, b = bt / T_;
    const float* p = k + (size_t)row * HD;
    float x1a = p[l], x1b = p[l+32], x2a = p[l+64], x2b = p[l+96];
    float ss = x1a*x1a + x1b*x1b + x2a*x2a + x2b*x2b;
    #pragma unroll
    for (int o = 16; o; o >>= 1) ss += __shfl_xor_sync(0xffffffffu, ss, o);
    float r = rsqrtf(ss * (1.0f/HD) + EPSF);
    x1a *= r; x1b *= r; x2a *= r; x2b *= r;
    float c1 = g_cos[t*(HD/2)+l],    s1 = g_sin[t*(HD/2)+l];
    float c2 = g_cos[t*(HD/2)+l+32], s2 = g_sin[t*(HD/2)+l+32];
    float* o = g_kT + ((size_t)(b*NKV + kv) * HD) * T_ + t;
    o[(size_t)(l   )*T_] =  x1a*c1 + x2a*s1;
    o[(size_t)(l+32)*T_] =  x1b*c2 + x2b*s2;
    o[(size_t)(l+64)*T_] = -x1a*s1 + x2a*c1;
    o[(size_t)(l+96)*T_] = -x1b*s2 + x2b*c2;
}

// ---------------- SGEMM NT: C[M,N] = A[M,K] @ B[N,K]^T (row-major, K inner) ----------------
__global__ void __launch_bounds__(256) sgemm_nt_kernel(
    const float* __restrict__ A, const float* __restrict__ B,
    float* __restrict__ C, int M, int N, int K)
{
    __shared__ float As[8][128];
    __shared__ float Bs[8][128];
    int tid = threadIdx.x;
    int bm = blockIdx.y * 128, bn = blockIdx.x * 128;
    int lr = tid >> 1;                // 0..127
    int lk = (tid & 1) * 4;           // 0 or 4
    const float* Ap = A + (size_t)(bm + lr) * K + lk;
    const float* Bp = B + (size_t)(bn + lr) * K + lk;
    int tx = tid & 15, ty = tid >> 4;
    float acc[8][8];
    #pragma unroll
    for (int i = 0; i < 8; i++)
        #pragma unroll
        for (int j = 0; j < 8; j++) acc[i][j] = 0.f;

    for (int k0 = 0; k0 < K; k0 += 8) {
        float4 av = *(const float4*)(Ap + k0);
        float4 bv = *(const float4*)(Bp + k0);
        __syncthreads();
        As[lk+0][lr] = av.x; As[lk+1][lr] = av.y; As[lk+2][lr] = av.z; As[lk+3][lr] = av.w;
        Bs[lk+0][lr] = bv.x; Bs[lk+1][lr] = bv.y; Bs[lk+2][lr] = bv.z; Bs[lk+3][lr] = bv.w;
        __syncthreads();
        #pragma unroll
        for (int kk = 0; kk < 8; kk++) {
            float a[8], b[8];
            *(float4*)&a[0] = *(const float4*)&As[kk][ty*8];
            *(float4*)&a[4] = *(const float4*)&As[kk][ty*8+4];
            *(float4*)&b[0] = *(const float4*)&Bs[kk][tx*8];
            *(float4*)&b[4] = *(const float4*)&Bs[kk][tx*8+4];
            #pragma unroll
            for (int i = 0; i < 8; i++)
                #pragma unroll
                for (int j = 0; j < 8; j++)
                    acc[i][j] += a[i] * b[j];
        }
    }
    #pragma unroll
    for (int i = 0; i < 8; i++) {
        float* Cp = C + (size_t)(bm + ty*8 + i) * N + bn + tx*8;
        *(float4*)Cp       = make_float4(acc[i][0], acc[i][1], acc[i][2], acc[i][3]);
        *(float4*)(Cp + 4) = make_float4(acc[i][4], acc[i][5], acc[i][6], acc[i][7]);
    }
}

// ---------------- Flash attention (causal GQA), fp32 ----------------
// block: 256 thr (8 warps); BM=32 q rows (4/warp), BN=128 keys/tile
#define FBM 32
#define FBN 128
#define QP  36   // transposed smem pitch (16B-aligned float4 reads at 4*w)

#define FLASH_SMEM ((HD*QP + FBN*HD + FBN*HD + FBN*QP) * 4)

__global__ void __launch_bounds__(256) flash_kernel(
    const float* __restrict__ q, const float* __restrict__ kT,
    const float* __restrict__ v, float* __restrict__ y)
{
    extern __shared__ float sm[];
    float* QsT = sm;                         // [HD][QP]   q transposed, pre-scaled
    float* Ks  = sm + HD*QP;                 // [HD][FBN]  K tile, d-major
    float* Vs  = Ks + FBN*HD;                // [FBN][HD]  V tile, j-major
    float* PsT = Vs + FBN*HD;                // [FBN][QP]  probs transposed

    int tid = threadIdx.x, w = tid >> 5, l = tid & 31;
    int qt = blockIdx.x, h = blockIdx.y, b = blockIdx.z;
    int t0 = qt * FBM;
    int kv = h / (NH / NKV);
    const float scale = 0.08838834764831843f;  // 1/sqrt(128)

    // load Q tile transposed + scaled
    const float* qbase = q + ((size_t)(b*T_ + t0) * NH + h) * HD;
    #pragma unroll
    for (int it = 0; it < 4; it++) {
        int vec = it*256 + tid;          // 0..1023
        int r  = vec >> 5;               // row 0..31
        int dv = vec & 31;               // float4 idx
        float4 qq = *(const float4*)(qbase + (size_t)r * NH * HD + 4*dv);
        QsT[(4*dv+0)*QP + r] = qq.x * scale;
        QsT[(4*dv+1)*QP + r] = qq.y * scale;
        QsT[(4*dv+2)*QP + r] = qq.z * scale;
        QsT[(4*dv+3)*QP + r] = qq.w * scale;
    }

    float  m_i[4], l_i[4];
    float4 acc[4];
    #pragma unroll
    for (int i = 0; i < 4; i++) { m_i[i] = -CUDART_INF_F; l_i[i] = 0.f; acc[i] = make_float4(0,0,0,0); }

    int nkt = (t0 >> 7) + 1;  // key tiles needed (covers t0+31 since t0 % 128 <= 96)
    const float* kTbase = kT + ((size_t)(b*NKV + kv) * HD) * T_;
    const float* vbase  = v + (((size_t)b * T_) * NKV + kv) * HD;

    for (int kt = 0; kt < nkt; kt++) {
        int kb = kt * FBN;
        __syncthreads();   // also covers QsT store (first iter) and PsT/Vs reuse
        // cooperative load of K (transposed source -> conflict-free) and V (natural)
        #pragma unroll
        for (int it = 0; it < 16; it++) {
            int vec = it*256 + tid;       // 0..4095
            int r  = vec >> 5;            // d for K, j for V
            int cv = vec & 31;            // float4 idx
            float4 kk = *(const float4*)(kTbase + (size_t)r * T_ + kb + 4*cv);
            *(float4*)&Ks[r*FBN + 4*cv] = kk;
            float4 vv = *(const float4*)(vbase + (size_t)(kb + r) * NKV * HD + 4*cv);
            *(float4*)&Vs[r*HD + 4*cv] = vv;
        }
        __syncthreads();

        // ---- S = Q K^T : lane owns keys {l, l+32, l+64, l+96}, warp owns rows 4w..4w+3
        float s[4][4];
        #pragma unroll
        for (int i = 0; i < 4; i++)
            #pragma unroll
            for (int c = 0; c < 4; c++) s[i][c] = 0.f;

        #pragma unroll 4
        for (int d = 0; d < HD; d++) {
            float4 qv = *(const float4*)&QsT[d*QP + 4*w];
            float k0v = Ks[d*FBN + l];
            float k1v = Ks[d*FBN + l + 32];
            float k2v = Ks[d*FBN + l + 64];
            float k3v = Ks[d*FBN + l + 96];
            s[0][0] += qv.x*k0v; s[0][1] += qv.x*k1v; s[0][2] += qv.x*k2v; s[0][3] += qv.x*k3v;
            s[1][0] += qv.y*k0v; s[1][1] += qv.y*k1v; s[1][2] += qv.y*k2v; s[1][3] += qv.y*k3v;
            s[2][0] += qv.z*k0v; s[2][1] += qv.z*k1v; s[2][2] += qv.z*k2v; s[2][3] += qv.z*k3v;
            s[3][0] += qv.w*k0v; s[3][1] += qv.w*k1v; s[3][2] += qv.w*k2v; s[3][3] += qv.w*k3v;
        }

        // ---- online softmax per row
        #pragma unroll
        for (int i = 0; i < 4; i++) {
            int tg = t0 + 4*w + i;
            float sv[4];
            #pragma unroll
            for (int c = 0; c < 4; c++) {
                int jg = kb + l + 32*c;
                sv[c] = (jg <= tg) ? s[i][c] : -CUDART_INF_F;
            }
            float mx = fmaxf(fmaxf(sv[0], sv[1]), fmaxf(sv[2], sv[3]));
            #pragma unroll
            for (int o = 16; o; o >>= 1) mx = fmaxf(mx, __shfl_xor_sync(0xffffffffu, mx, o));
            float m_new = fmaxf(m_i[i], mx);
            float alpha = __expf(m_i[i] - m_new);
            float ps = 0.f;
            #pragma unroll
            for (int c = 0; c < 4; c++) {
                float pp = __expf(sv[c] - m_new);
                PsT[(l + 32*c)*QP + 4*w + i] = pp;
                ps += pp;
            }
            #pragma unroll
            for (int o = 16; o; o >>= 1) ps += __shfl_xor_sync(0xffffffffu, ps, o);
            l_i[i] = l_i[i] * alpha + ps;
            m_i[i] = m_new;
            acc[i].x *= alpha; acc[i].y *= alpha; acc[i].z *= alpha; acc[i].w *= alpha;
        }
        __syncwarp();

        // ---- O += P V : lane owns dims 4l..4l+3
        #pragma unroll 2
        for (int j = 0; j < FBN; j++) {
            float4 pv = *(const float4*)&PsT[j*QP + 4*w];
            float4 vv = *(const float4*)&Vs[j*HD + 4*l];
            acc[0].x += pv.x*vv.x; acc[0].y += pv.x*vv.y; acc[0].z += pv.x*vv.z; acc[0].w += pv.x*vv.w;
            acc[1].x += pv.y*vv.x; acc[1].y += pv.y*vv.y; acc[1].z += pv.y*vv.z; acc[1].w += pv.y*vv.w;
            acc[2].x += pv.z*vv.x; acc[2].y += pv.z*vv.y; acc[2].z += pv.z*vv.z; acc[2].w += pv.z*vv.w;
            acc[3].x += pv.w*vv.x; acc[3].y += pv.w*vv.y; acc[3].z += pv.w*vv.z; acc[3].w += pv.w*vv.w;
        }
    }

    // ---- epilogue: normalize and store
    float* ybase = y + ((size_t)(b*T_ + t0 + 4*w) * NH + h) * HD + 4*l;
    #pragma unroll
    for (int i = 0; i < 4; i++) {
        float inv = 1.f / l_i[i];
        float4 o = make_float4(acc[i].x*inv, acc[i].y*inv, acc[i].z*inv, acc[i].w*inv);
        *(float4*)(ybase + (size_t)i * NH * HD) = o;
    }
}

// ---------------- launch ----------------
extern "C" void kernel_launch(void* const* d_in, const int* in_sizes, int n_in,
                              void* d_out, int out_size) {
    const float* x  = (const float*)d_in[0];
    const float* Wq = (const float*)d_in[1];
    const float* Wk = (const float*)d_in[2];
    const float* Wv = (const float*)d_in[3];
    const float* Wp = (const float*)d_in[4];
    const float* qg = (const float*)d_in[5];
    float* out = (float*)d_out;

    float *q, *k, *kT, *v, *y;
    cudaGetSymbolAddress((void**)&q,  g_q);
    cudaGetSymbolAddress((void**)&k,  g_k);
    cudaGetSymbolAddress((void**)&kT, g_kT);
    cudaGetSymbolAddress((void**)&v,  g_v);
    cudaGetSymbolAddress((void**)&y,  g_y);

    cudaFuncSetAttribute(flash_kernel, cudaFuncAttributeMaxDynamicSharedMemorySize, FLASH_SMEM);

    const int M = B_ * T_;  // 4096

    rope_table_kernel<<<(T_*(HD/2) + 255)/256, 256>>>();

    sgemm_nt_kernel<<<dim3(DIM/128, M/128), 256>>>(x, Wq, q, M, DIM, DIM);
    sgemm_nt_kernel<<<dim3(KD /128, M/128), 256>>>(x, Wk, k, M, KD,  DIM);
    sgemm_nt_kernel<<<dim3(KD /128, M/128), 256>>>(x, Wv, v, M, KD,  DIM);

    rmsnorm_rope_q_kernel<<<(B_*T_*NH)/8, 256>>>(q, qg);
    rmsnorm_rope_k_kernel<<<(B_*T_*NKV)/8, 256>>>(k);

    flash_kernel<<<dim3(T_/FBM, NH, B_), 256, FLASH_SMEM>>>(q, kT, v, y);

    sgemm_nt_kernel<<<dim3(DIM/128, M/128), 256>>>(y, Wp, out, M, DIM, DIM);
}

// round 4
// speedup vs baseline: 1.1240x; 1.1240x over previous
#include <cuda_runtime.h>
#include <math.h>
#include <math_constants.h>

#define B_   2
#define T_   2048
#define DIM  2048
#define NH   16
#define NKV  4
#define HD   128
#define KD   512           // NKV*HD
#define EPSF 1.1920928955078125e-07f

typedef unsigned long long ull;

// ---------------- f32x2 packed helpers (sm_100+) ----------------
__device__ __forceinline__ ull pk(float lo, float hi) {
    ull r; asm("mov.b64 %0,{%1,%2};" : "=l"(r) : "f"(lo), "f"(hi)); return r;
}
__device__ __forceinline__ void unpk(ull v, float& lo, float& hi) {
    asm("mov.b64 {%0,%1},%2;" : "=f"(lo), "=f"(hi) : "l"(v));
}
__device__ __forceinline__ void fma2(ull& d, ull a, ull b) {
    asm("fma.rn.f32x2 %0,%1,%2,%0;" : "+l"(d) : "l"(a), "l"(b));
}
__device__ __forceinline__ ull mul2(ull a, ull b) {
    ull r; asm("mul.rn.f32x2 %0,%1,%2;" : "=l"(r) : "l"(a), "l"(b)); return r;
}

// ---------------- scratch (static device memory; no allocation) ----------------
__device__ float g_q [B_*T_*DIM];        // q after proj / norm / rope (natural)
__device__ float g_k [B_*T_*KD];         // k after proj (natural)
__device__ float g_kT[B_*NKV*HD*T_];     // k after norm/rope, transposed [b][kv][d][t]
__device__ float g_v [B_*T_*KD];         // v (natural)
__device__ float g_y [B_*T_*DIM];        // attention output (natural)
__device__ float g_cos[T_*(HD/2)];
__device__ float g_sin[T_*(HD/2)];

// ---------------- RoPE tables (double, matching numpy f64 path) ----------------
__global__ void rope_table_kernel() {
    int idx = blockIdx.x * blockDim.x + threadIdx.x;
    if (idx >= T_ * (HD/2)) return;
    int t = idx / (HD/2), j = idx % (HD/2);
    double base = 10000.0 * exp2((double)HD / (double)(HD - 2));
    double e    = (double)(2 * j) / (double)HD;
    double invf = 1.0 / pow(base, e);
    double fr   = (double)t * invf;
    g_cos[idx] = (float)cos(fr);
    g_sin[idx] = (float)sin(fr);
}

// ---------------- RMSNorm + RoPE (+gain) for Q ----------------
__global__ void rmsnorm_rope_q_kernel(float* __restrict__ q, const float* __restrict__ gain) {
    int w = threadIdx.x >> 5, l = threadIdx.x & 31;
    int row = blockIdx.x * 8 + w;           // (b*T + t)*NH + h
    int h = row % NH;
    int t = (row / NH) % T_;
    float* p = q + (size_t)row * HD;
    float x1a = p[l], x1b = p[l+32], x2a = p[l+64], x2b = p[l+96];
    float ss = x1a*x1a + x1b*x1b + x2a*x2a + x2b*x2b;
    #pragma unroll
    for (int o = 16; o; o >>= 1) ss += __shfl_xor_sync(0xffffffffu, ss, o);
    float r = rsqrtf(ss * (1.0f/HD) + EPSF);
    x1a *= r; x1b *= r; x2a *= r; x2b *= r;
    float c1 = g_cos[t*(HD/2)+l],    s1 = g_sin[t*(HD/2)+l];
    float c2 = g_cos[t*(HD/2)+l+32], s2 = g_sin[t*(HD/2)+l+32];
    float gn = gain[h];
    p[l]    = ( x1a*c1 + x2a*s1) * gn;
    p[l+32] = ( x1b*c2 + x2b*s2) * gn;
    p[l+64] = (-x1a*s1 + x2a*c1) * gn;
    p[l+96] = (-x1b*s2 + x2b*c2) * gn;
}

// ---------------- RMSNorm + RoPE for K, writes transposed layout ----------------
__global__ void rmsnorm_rope_k_kernel(const float* __restrict__ k) {
    int w = threadIdx.x >> 5, l = threadIdx.x & 31;
    int row = blockIdx.x * 8 + w;           // (b*T + t)*NKV + kv
    int kv = row % NKV;
    int bt = row / NKV;
    int t = bt % T_, b = bt / T_;
    const float* p = k + (size_t)row * HD;
    float x1a = p[l], x1b = p[l+32], x2a = p[l+64], x2b = p[l+96];
    float ss = x1a*x1a + x1b*x1b + x2a*x2a + x2b*x2b;
    #pragma unroll
    for (int o = 16; o; o >>= 1) ss += __shfl_xor_sync(0xffffffffu, ss, o);
    float r = rsqrtf(ss * (1.0f/HD) + EPSF);
    x1a *= r; x1b *= r; x2a *= r; x2b *= r;
    float c1 = g_cos[t*(HD/2)+l],    s1 = g_sin[t*(HD/2)+l];
    float c2 = g_cos[t*(HD/2)+l+32], s2 = g_sin[t*(HD/2)+l+32];
    float* o = g_kT + ((size_t)(b*NKV + kv) * HD) * T_ + t;
    o[(size_t)(l   )*T_] =  x1a*c1 + x2a*s1;
    o[(size_t)(l+32)*T_] =  x1b*c2 + x2b*s2;
    o[(size_t)(l+64)*T_] = -x1a*s1 + x2a*c1;
    o[(size_t)(l+96)*T_] = -x1b*s2 + x2b*c2;
}

// ---------------- SGEMM NT with f32x2, K-tile 16, double-buffered ----------------
// C[M,N] = A[M,K] @ B[N,K]^T ; block tile 128x128, 256 threads, 8x8/thread.
__device__ __forceinline__ void gemm_core_f32x2(
    const float* __restrict__ A, const float* __restrict__ B, float* __restrict__ C,
    int N, int K, int bm, int bn)
{
    __shared__ float As[2][16][128];
    __shared__ float Bs[2][16][128];
    int tid = threadIdx.x;
    int r = tid >> 1;                 // 0..127
    int half = tid & 1;               // k-offset 8*half
    const float* Ap = A + (size_t)(bm + r) * K + 8*half;
    const float* Bp = B + (size_t)(bn + r) * K + 8*half;
    int tx = tid & 15, ty = tid >> 4;

    ull acc2[8][4];
    #pragma unroll
    for (int i = 0; i < 8; i++)
        #pragma unroll
        for (int j = 0; j < 4; j++) acc2[i][j] = 0ULL;

    float4 a0, a1, b0, b1;
    a0 = *(const float4*)(Ap);     a1 = *(const float4*)(Ap + 4);
    b0 = *(const float4*)(Bp);     b1 = *(const float4*)(Bp + 4);
    int p = 0;
    {
        int kb = 8*half;
        As[0][kb+0][r]=a0.x; As[0][kb+1][r]=a0.y; As[0][kb+2][r]=a0.z; As[0][kb+3][r]=a0.w;
        As[0][kb+4][r]=a1.x; As[0][kb+5][r]=a1.y; As[0][kb+6][r]=a1.z; As[0][kb+7][r]=a1.w;
        Bs[0][kb+0][r]=b0.x; Bs[0][kb+1][r]=b0.y; Bs[0][kb+2][r]=b0.z; Bs[0][kb+3][r]=b0.w;
        Bs[0][kb+4][r]=b1.x; Bs[0][kb+5][r]=b1.y; Bs[0][kb+6][r]=b1.z; Bs[0][kb+7][r]=b1.w;
    }
    __syncthreads();

    int nk = K / 16;
    for (int t = 0; t < nk; t++) {
        if (t + 1 < nk) {
            const float* Ap2 = Ap + (size_t)(t+1)*16;
            const float* Bp2 = Bp + (size_t)(t+1)*16;
            a0 = *(const float4*)(Ap2);  a1 = *(const float4*)(Ap2 + 4);
            b0 = *(const float4*)(Bp2);  b1 = *(const float4*)(Bp2 + 4);
        }
        #pragma unroll
        for (int kk = 0; kk < 16; kk++) {
            float a[8], b[8];
            *(float4*)&a[0] = *(const float4*)&As[p][kk][ty*8];
            *(float4*)&a[4] = *(const float4*)&As[p][kk][ty*8+4];
            *(float4*)&b[0] = *(const float4*)&Bs[p][kk][tx*8];
            *(float4*)&b[4] = *(const float4*)&Bs[p][kk][tx*8+4];
            ull b2[4];
            #pragma unroll
            for (int j = 0; j < 4; j++) b2[j] = pk(b[2*j], b[2*j+1]);
            #pragma unroll
            for (int i = 0; i < 8; i++) {
                ull a2 = pk(a[i], a[i]);
                fma2(acc2[i][0], a2, b2[0]);
                fma2(acc2[i][1], a2, b2[1]);
                fma2(acc2[i][2], a2, b2[2]);
                fma2(acc2[i][3], a2, b2[3]);
            }
        }
        if (t + 1 < nk) {
            int q = p ^ 1, kb = 8*half;
            As[q][kb+0][r]=a0.x; As[q][kb+1][r]=a0.y; As[q][kb+2][r]=a0.z; As[q][kb+3][r]=a0.w;
            As[q][kb+4][r]=a1.x; As[q][kb+5][r]=a1.y; As[q][kb+6][r]=a1.z; As[q][kb+7][r]=a1.w;
            Bs[q][kb+0][r]=b0.x; Bs[q][kb+1][r]=b0.y; Bs[q][kb+2][r]=b0.z; Bs[q][kb+3][r]=b0.w;
            Bs[q][kb+4][r]=b1.x; Bs[q][kb+5][r]=b1.y; Bs[q][kb+6][r]=b1.z; Bs[q][kb+7][r]=b1.w;
            __syncthreads();
            p = q;
        }
    }
    #pragma unroll
    for (int i = 0; i < 8; i++) {
        float c[8];
        unpk(acc2[i][0], c[0], c[1]); unpk(acc2[i][1], c[2], c[3]);
        unpk(acc2[i][2], c[4], c[5]); unpk(acc2[i][3], c[6], c[7]);
        float* Cp = C + (size_t)(bm + ty*8 + i) * N + bn + tx*8;
        *(float4*)Cp       = make_float4(c[0], c[1], c[2], c[3]);
        *(float4*)(Cp + 4) = make_float4(c[4], c[5], c[6], c[7]);
    }
}

__global__ void __launch_bounds__(256, 2) sgemm_f32x2_kernel(
    const float* __restrict__ A, const float* __restrict__ B, float* __restrict__ C,
    int N, int K)
{
    gemm_core_f32x2(A, B, C, N, K, blockIdx.y * 128, blockIdx.x * 128);
}

// merged K+V projection: blockIdx.x in [0,8): 0-3 -> Wk/g_k, 4-7 -> Wv/g_v
__global__ void __launch_bounds__(256, 2) sgemm_kv_kernel(
    const float* __restrict__ A, const float* __restrict__ Wk, const float* __restrict__ Wv,
    float* __restrict__ ko, float* __restrict__ vo, int K)
{
    int bx = blockIdx.x;
    const float* Bm = (bx < 4) ? Wk : Wv;
    float*       Cm = (bx < 4) ? ko : vo;
    gemm_core_f32x2(A, Bm, Cm, KD, K, blockIdx.y * 128, (bx & 3) * 128);
}

// ---------------- Flash attention (causal GQA), fp32 with f32x2 ----------------
// block: 256 thr (8 warps); BM=32 q rows (4/warp), BN=128 keys/tile
// lane owns keys 4l..4l+3 (consecutive); Q and P stored DUPLICATED in smem
#define FBM 32
#define FBN 128
#define QP2 66   // duplicated pitch (floats); word stride 66 -> 2-way max on stores

#define QS_SZ  (HD  * QP2)      // 8448 floats
#define KS_SZ  (HD  * FBN)      // 16384
#define VS_SZ  (FBN * HD)       // 16384
#define PS_SZ  (FBN * QP2)      // 8448
#define FLASH_SMEM ((QS_SZ + KS_SZ + VS_SZ + PS_SZ) * 4)   // 198656 B

__global__ void __launch_bounds__(256) flash_kernel(
    const float* __restrict__ q, const float* __restrict__ kT,
    const float* __restrict__ v, float* __restrict__ y)
{
    extern __shared__ float sm[];
    float* QsT = sm;                 // [HD][QP2]  q dup'd: cols 2r,2r+1 both hold q_r (pre-scaled)
    float* Ks  = sm + QS_SZ;         // [HD][FBN]  K tile, d-major
    float* Vs  = Ks + KS_SZ;         // [FBN][HD]  V tile, j-major
    float* PsT = Vs + VS_SZ;         // [FBN][QP2] probs dup'd, row index = c*32+l for key 4l+c

    int tid = threadIdx.x, w = tid >> 5, l = tid & 31;
    int qt = blockIdx.x, h = blockIdx.y, b = blockIdx.z;
    int t0 = qt * FBM;
    int kv = h / (NH / NKV);
    const float scale = 0.08838834764831843f;  // 1/sqrt(128)

    // load Q tile transposed + scaled + duplicated
    const float* qbase = q + ((size_t)(b*T_ + t0) * NH + h) * HD;
    #pragma unroll
    for (int it = 0; it < 4; it++) {
        int vec = it*256 + tid;          // 0..1023
        int r  = vec >> 5;               // row 0..31
        int dv = vec & 31;               // float4 idx
        float4 qq = *(const float4*)(qbase + (size_t)r * NH * HD + 4*dv);
        float v0 = qq.x*scale, v1 = qq.y*scale, v2 = qq.z*scale, v3 = qq.w*scale;
        *(ull*)&QsT[(4*dv+0)*QP2 + 2*r] = pk(v0, v0);
        *(ull*)&QsT[(4*dv+1)*QP2 + 2*r] = pk(v1, v1);
        *(ull*)&QsT[(4*dv+2)*QP2 + 2*r] = pk(v2, v2);
        *(ull*)&QsT[(4*dv+3)*QP2 + 2*r] = pk(v3, v3);
    }

    float m_i[4], l_i[4];
    ull acc2[4][2];
    #pragma unroll
    for (int i = 0; i < 4; i++) {
        m_i[i] = -CUDART_INF_F; l_i[i] = 0.f;
        acc2[i][0] = 0ULL; acc2[i][1] = 0ULL;
    }

    int nkt = (t0 >> 7) + 1;
    const float* kTbase = kT + ((size_t)(b*NKV + kv) * HD) * T_;
    const float* vbase  = v + (((size_t)b * T_) * NKV + kv) * HD;

    for (int kt = 0; kt < nkt; kt++) {
        int kb = kt * FBN;
        __syncthreads();   // covers QsT store (first iter) and Ks/Vs reuse
        #pragma unroll
        for (int it = 0; it < 16; it++) {
            int vec = it*256 + tid;       // 0..4095
            int rr = vec >> 5;            // d for K, j for V
            int cv = vec & 31;            // float4 idx
            float4 kk = *(const float4*)(kTbase + (size_t)rr * T_ + kb + 4*cv);
            *(float4*)&Ks[rr*FBN + 4*cv] = kk;
            float4 vv = *(const float4*)(vbase + (size_t)(kb + rr) * NKV * HD + 4*cv);
            *(float4*)&Vs[rr*HD + 4*cv] = vv;
        }
        __syncthreads();

        // ---- S = Q K^T : lane owns keys 4l..4l+3, warp owns rows 4w..4w+3
        ull s2[4][2];
        #pragma unroll
        for (int i = 0; i < 4; i++) { s2[i][0] = 0ULL; s2[i][1] = 0ULL; }

        #pragma unroll 4
        for (int d = 0; d < HD; d++) {
            ull q0 = *(const ull*)&QsT[d*QP2 + 8*w];     // (q_r, q_r) dup, broadcast
            ull q1 = *(const ull*)&QsT[d*QP2 + 8*w + 2];
            ull q2 = *(const ull*)&QsT[d*QP2 + 8*w + 4];
            ull q3 = *(const ull*)&QsT[d*QP2 + 8*w + 6];
            float4 kvv = *(const float4*)&Ks[d*FBN + 4*l];
            ull k2a = pk(kvv.x, kvv.y);
            ull k2b = pk(kvv.z, kvv.w);
            fma2(s2[0][0], q0, k2a); fma2(s2[0][1], q0, k2b);
            fma2(s2[1][0], q1, k2a); fma2(s2[1][1], q1, k2b);
            fma2(s2[2][0], q2, k2a); fma2(s2[2][1], q2, k2b);
            fma2(s2[3][0], q3, k2a); fma2(s2[3][1], q3, k2b);
        }

        // ---- online softmax per row
        #pragma unroll
        for (int i = 0; i < 4; i++) {
            int tg = t0 + 4*w + i;
            float sv[4];
            unpk(s2[i][0], sv[0], sv[1]);
            unpk(s2[i][1], sv[2], sv[3]);
            #pragma unroll
            for (int c = 0; c < 4; c++) {
                int jg = kb + 4*l + c;
                if (jg > tg) sv[c] = -CUDART_INF_F;
            }
            float mx = fmaxf(fmaxf(sv[0], sv[1]), fmaxf(sv[2], sv[3]));
            #pragma unroll
            for (int o = 16; o; o >>= 1) mx = fmaxf(mx, __shfl_xor_sync(0xffffffffu, mx, o));
            float m_new = fmaxf(m_i[i], mx);
            float alpha = __expf(m_i[i] - m_new);
            float ps = 0.f;
            #pragma unroll
            for (int c = 0; c < 4; c++) {
                float pp = __expf(sv[c] - m_new);
                *(ull*)&PsT[(c*32 + l)*QP2 + 2*(4*w + i)] = pk(pp, pp);
                ps += pp;
            }
            #pragma unroll
            for (int o = 16; o; o >>= 1) ps += __shfl_xor_sync(0xffffffffu, ps, o);
            l_i[i] = l_i[i] * alpha + ps;
            m_i[i] = m_new;
            ull al2 = pk(alpha, alpha);
            acc2[i][0] = mul2(acc2[i][0], al2);
            acc2[i][1] = mul2(acc2[i][1], al2);
        }
        __syncwarp();

        // ---- O += P V : lane owns dims 4l..4l+3 (as 2 f32x2 pairs)
        #pragma unroll 4
        for (int s = 0; s < FBN; s++) {
            int j = 4*(s & 31) + (s >> 5);      // storage row s holds key j
            ull p0 = *(const ull*)&PsT[s*QP2 + 8*w];     // (p,p) dup, broadcast
            ull p1 = *(const ull*)&PsT[s*QP2 + 8*w + 2];
            ull p2 = *(const ull*)&PsT[s*QP2 + 8*w + 4];
            ull p3 = *(const ull*)&PsT[s*QP2 + 8*w + 6];
            float4 vv = *(const float4*)&Vs[j*HD + 4*l];
            ull v2a = pk(vv.x, vv.y);
            ull v2b = pk(vv.z, vv.w);
            fma2(acc2[0][0], p0, v2a); fma2(acc2[0][1], p0, v2b);
            fma2(acc2[1][0], p1, v2a); fma2(acc2[1][1], p1, v2b);
            fma2(acc2[2][0], p2, v2a); fma2(acc2[2][1], p2, v2b);
            fma2(acc2[3][0], p3, v2a); fma2(acc2[3][1], p3, v2b);
        }
    }

    // ---- epilogue: normalize and store
    float* ybase = y + ((size_t)(b*T_ + t0 + 4*w) * NH + h) * HD + 4*l;
    #pragma unroll
    for (int i = 0; i < 4; i++) {
        float inv = 1.f / l_i[i];
        float o0, o1, o2, o3;
        unpk(acc2[i][0], o0, o1);
        unpk(acc2[i][1], o2, o3);
        *(float4*)(ybase + (size_t)i * NH * HD) = make_float4(o0*inv, o1*inv, o2*inv, o3*inv);
    }
}

// ---------------- launch ----------------
extern "C" void kernel_launch(void* const* d_in, const int* in_sizes, int n_in,
                              void* d_out, int out_size) {
    const float* x  = (const float*)d_in[0];
    const float* Wq = (const float*)d_in[1];
    const float* Wk = (const float*)d_in[2];
    const float* Wv = (const float*)d_in[3];
    const float* Wp = (const float*)d_in[4];
    const float* qg = (const float*)d_in[5];
    float* out = (float*)d_out;

    float *q, *k, *kT, *v, *y;
    cudaGetSymbolAddress((void**)&q,  g_q);
    cudaGetSymbolAddress((void**)&k,  g_k);
    cudaGetSymbolAddress((void**)&kT, g_kT);
    cudaGetSymbolAddress((void**)&v,  g_v);
    cudaGetSymbolAddress((void**)&y,  g_y);

    cudaFuncSetAttribute(flash_kernel, cudaFuncAttributeMaxDynamicSharedMemorySize, FLASH_SMEM);

    const int M = B_ * T_;  // 4096

    rope_table_kernel<<<(T_*(HD/2) + 255)/256, 256>>>();

    sgemm_f32x2_kernel<<<dim3(DIM/128, M/128), 256>>>(x, Wq, q, DIM, DIM);
    sgemm_kv_kernel  <<<dim3(8,       M/128), 256>>>(x, Wk, Wv, k, v, DIM);

    rmsnorm_rope_q_kernel<<<(B_*T_*NH)/8, 256>>>(q, qg);
    rmsnorm_rope_k_kernel<<<(B_*T_*NKV)/8, 256>>>(k);

    flash_kernel<<<dim3(T_/FBM, NH, B_), 256, FLASH_SMEM>>>(q, kT, v, y);

    sgemm_f32x2_kernel<<<dim3(DIM/128, M/128), 256>>>(y, Wp, out, DIM, DIM);
}